// round 3
// baseline (speedup 1.0000x reference)
#include <cuda_runtime.h>

#define BATCH   8192
#define FPP     32
#define FT_OUT  1024
#define N_VFEAT 768
#define NTHREADS 256

__device__ __forceinline__ float clamp01(float x) {
    return __saturatef(x);   // min(max(x,0),1) — single SASS op
}

__global__ __launch_bounds__(NTHREADS, 4)
void nnue_fused_kernel(
    const float* __restrict__ values,
    const int*   __restrict__ stm_feat,
    const int*   __restrict__ nstm_feat,
    const float* __restrict__ W_ft,
    const float* __restrict__ b_ft,
    const float* __restrict__ W_fft,
    const float* __restrict__ b_fft,
    const float* __restrict__ W_out,
    const float* __restrict__ b_out,
    float*       __restrict__ out)
{
    const int b = blockIdx.x;
    const int t = threadIdx.x;

    __shared__ int   s_stm[FPP];
    __shared__ int   s_nstm[FPP];
    __shared__ float s_val[FPP];
    __shared__ float s_red[NTHREADS / 32];

    if (t < FPP) {
        s_stm[t]  = stm_feat[b * FPP + t];
        s_nstm[t] = nstm_feat[b * FPP + t];
        s_val[t]  = values[b * FPP + t];
    }
    __syncthreads();

    const int col = t * 4;

    float4 acc_s = make_float4(0.f, 0.f, 0.f, 0.f);
    float4 acc_n = make_float4(0.f, 0.f, 0.f, 0.f);

    #pragma unroll 4
    for (int k = 0; k < FPP; k++) {
        const float v  = s_val[k];
        const int   fs = s_stm[k];
        const int   fn = s_nstm[k];

        const float4 ws  = *reinterpret_cast<const float4*>(W_ft  + (size_t)fs * FT_OUT + col);
        const float4 wfs = *reinterpret_cast<const float4*>(W_fft + (size_t)(fs % N_VFEAT) * FT_OUT + col);
        const float4 wn  = *reinterpret_cast<const float4*>(W_ft  + (size_t)fn * FT_OUT + col);
        const float4 wfn = *reinterpret_cast<const float4*>(W_fft + (size_t)(fn % N_VFEAT) * FT_OUT + col);

        acc_s.x = fmaf(v, ws.x + wfs.x, acc_s.x);
        acc_s.y = fmaf(v, ws.y + wfs.y, acc_s.y);
        acc_s.z = fmaf(v, ws.z + wfs.z, acc_s.z);
        acc_s.w = fmaf(v, ws.w + wfs.w, acc_s.w);

        acc_n.x = fmaf(v, wn.x + wfn.x, acc_n.x);
        acc_n.y = fmaf(v, wn.y + wfn.y, acc_n.y);
        acc_n.z = fmaf(v, wn.z + wfn.z, acc_n.z);
        acc_n.w = fmaf(v, wn.w + wfn.w, acc_n.w);
    }

    // biases (added once)
    const float4 bft  = *reinterpret_cast<const float4*>(b_ft  + col);
    const float4 bfft = *reinterpret_cast<const float4*>(b_fft + col);
    acc_s.x += bft.x + bfft.x;  acc_s.y += bft.y + bfft.y;
    acc_s.z += bft.z + bfft.z;  acc_s.w += bft.w + bfft.w;
    acc_n.x += bft.x + bfft.x;  acc_n.y += bft.y + bfft.y;
    acc_n.z += bft.z + bfft.z;  acc_n.w += bft.w + bfft.w;

    // clamp [0,1] + fused dot with W_out (stm -> rows [0,1024), nstm -> [1024,2048))
    const float4 wo_s = *reinterpret_cast<const float4*>(W_out + col);
    const float4 wo_n = *reinterpret_cast<const float4*>(W_out + FT_OUT + col);

    float partial =
        clamp01(acc_s.x) * wo_s.x + clamp01(acc_s.y) * wo_s.y +
        clamp01(acc_s.z) * wo_s.z + clamp01(acc_s.w) * wo_s.w +
        clamp01(acc_n.x) * wo_n.x + clamp01(acc_n.y) * wo_n.y +
        clamp01(acc_n.z) * wo_n.z + clamp01(acc_n.w) * wo_n.w;

    // block reduction
    #pragma unroll
    for (int off = 16; off > 0; off >>= 1)
        partial += __shfl_xor_sync(0xFFFFFFFFu, partial, off);

    const int warp = t >> 5;
    const int lane = t & 31;
    if (lane == 0) s_red[warp] = partial;
    __syncthreads();

    if (warp == 0) {
        float v = (lane < NTHREADS / 32) ? s_red[lane] : 0.f;
        #pragma unroll
        for (int off = 4; off > 0; off >>= 1)
            v += __shfl_xor_sync(0xFFFFFFFFu, v, off);
        if (lane == 0) {
            const float z = v + b_out[0];
            out[b] = 1.0f / (1.0f + expf(-z));
        }
    }
}

extern "C" void kernel_launch(void* const* d_in, const int* in_sizes, int n_in,
                              void* d_out, int out_size) {
    // metadata order: values, stm_feat, nstm_feat, batch_idx, W_ft, b_ft,
    //                 W_fft, b_fft, W_out, b_out, size
    const float* values    = (const float*)d_in[0];
    const int*   stm_feat  = (const int*)  d_in[1];
    const int*   nstm_feat = (const int*)  d_in[2];
    // d_in[3] = batch_idx — layout implied (repeat(arange(B), FPP))
    const float* W_ft      = (const float*)d_in[4];
    const float* b_ft      = (const float*)d_in[5];
    const float* W_fft     = (const float*)d_in[6];
    const float* b_fft     = (const float*)d_in[7];
    const float* W_out     = (const float*)d_in[8];
    const float* b_out     = (const float*)d_in[9];
    float* out = (float*)d_out;

    nnue_fused_kernel<<<BATCH, NTHREADS>>>(
        values, stm_feat, nstm_feat, W_ft, b_ft, W_fft, b_fft, W_out, b_out, out);
}

// round 4
// speedup vs baseline: 1.8771x; 1.8771x over previous
#include <cuda_runtime.h>
#include <cuda_fp16.h>

#define BATCH   8192
#define FPP     32
#define FT_OUT  1024
#define N_FEAT  49152
#define N_VFEAT 768
#define MAIN_THREADS 128

// fp16 combined table: W_comb[r][c] = W_ft[r][c] + W_fft[r % 768][c]
// 49152 rows x 1024 cols x 2B = 100,663,296 bytes = 6,291,456 uint4
__device__ uint4 g_Wcomb[(size_t)N_FEAT * FT_OUT / 8];

__device__ __forceinline__ float clamp01(float x) { return __saturatef(x); }

// ---------------------------------------------------------------------------
// Kernel 1: build the combined fp16 table (runs every launch; deterministic).
// One thread per 4 elements. Streaming reads (evict-first) so the 201MB W_ft
// stream doesn't evict the freshly written W_comb from L2.
// ---------------------------------------------------------------------------
__global__ __launch_bounds__(256)
void combine_kernel(const float* __restrict__ W_ft,
                    const float* __restrict__ W_fft)
{
    const int i = blockIdx.x * 256 + threadIdx.x;   // 0 .. 12,582,911
    const int r = i >> 8;                           // row (1024/4 = 256 groups/row)
    const int c = (i & 255) << 2;                   // col base

    const float4 a = __ldcs(reinterpret_cast<const float4*>(W_ft  + (size_t)r * FT_OUT + c));
    const float4 v = __ldg (reinterpret_cast<const float4*>(W_fft + (size_t)(r % N_VFEAT) * FT_OUT + c));

    __half2 h0 = __floats2half2_rn(a.x + v.x, a.y + v.y);
    __half2 h1 = __floats2half2_rn(a.z + v.z, a.w + v.w);

    uint2 o;
    o.x = *reinterpret_cast<unsigned int*>(&h0);
    o.y = *reinterpret_cast<unsigned int*>(&h1);
    reinterpret_cast<uint2*>(g_Wcomb)[i] = o;
}

// ---------------------------------------------------------------------------
// Kernel 2: fused gather + bias + clamp + output dot + sigmoid.
// 1 CTA per batch element; 128 threads, each owning 8 columns (one uint4 =
// 8 fp16 per gathered row per side).
// ---------------------------------------------------------------------------
__global__ __launch_bounds__(MAIN_THREADS, 8)
void nnue_fused_kernel(
    const float* __restrict__ values,
    const int*   __restrict__ stm_feat,
    const int*   __restrict__ nstm_feat,
    const float* __restrict__ b_ft,
    const float* __restrict__ b_fft,
    const float* __restrict__ W_out,
    const float* __restrict__ b_out,
    float*       __restrict__ out)
{
    const int b = blockIdx.x;
    const int t = threadIdx.x;

    __shared__ int   s_stm[FPP];
    __shared__ int   s_nstm[FPP];
    __shared__ float s_val[FPP];
    __shared__ float s_red[MAIN_THREADS / 32];

    if (t < FPP) {
        s_stm[t]  = stm_feat[b * FPP + t];
        s_nstm[t] = nstm_feat[b * FPP + t];
        s_val[t]  = values[b * FPP + t];
    }
    __syncthreads();

    float acc_s[8], acc_n[8];
    #pragma unroll
    for (int i = 0; i < 8; i++) { acc_s[i] = 0.f; acc_n[i] = 0.f; }

    const uint4* __restrict__ Wc = g_Wcomb;

    #pragma unroll 4
    for (int k = 0; k < FPP; k++) {
        const float v  = s_val[k];
        const int   fs = s_stm[k];
        const int   fn = s_nstm[k];

        const uint4 us = Wc[(size_t)fs * (FT_OUT / 8) + t];
        const uint4 un = Wc[(size_t)fn * (FT_OUT / 8) + t];

        const float2 s0 = __half22float2(*reinterpret_cast<const __half2*>(&us.x));
        const float2 s1 = __half22float2(*reinterpret_cast<const __half2*>(&us.y));
        const float2 s2 = __half22float2(*reinterpret_cast<const __half2*>(&us.z));
        const float2 s3 = __half22float2(*reinterpret_cast<const __half2*>(&us.w));
        const float2 n0 = __half22float2(*reinterpret_cast<const __half2*>(&un.x));
        const float2 n1 = __half22float2(*reinterpret_cast<const __half2*>(&un.y));
        const float2 n2 = __half22float2(*reinterpret_cast<const __half2*>(&un.z));
        const float2 n3 = __half22float2(*reinterpret_cast<const __half2*>(&un.w));

        acc_s[0] = fmaf(v, s0.x, acc_s[0]);  acc_s[1] = fmaf(v, s0.y, acc_s[1]);
        acc_s[2] = fmaf(v, s1.x, acc_s[2]);  acc_s[3] = fmaf(v, s1.y, acc_s[3]);
        acc_s[4] = fmaf(v, s2.x, acc_s[4]);  acc_s[5] = fmaf(v, s2.y, acc_s[5]);
        acc_s[6] = fmaf(v, s3.x, acc_s[6]);  acc_s[7] = fmaf(v, s3.y, acc_s[7]);

        acc_n[0] = fmaf(v, n0.x, acc_n[0]);  acc_n[1] = fmaf(v, n0.y, acc_n[1]);
        acc_n[2] = fmaf(v, n1.x, acc_n[2]);  acc_n[3] = fmaf(v, n1.y, acc_n[3]);
        acc_n[4] = fmaf(v, n2.x, acc_n[4]);  acc_n[5] = fmaf(v, n2.y, acc_n[5]);
        acc_n[6] = fmaf(v, n3.x, acc_n[6]);  acc_n[7] = fmaf(v, n3.y, acc_n[7]);
    }

    // biases (fp32, exact), clamp, fused output dot
    const int col = t * 8;
    float partial = 0.f;
    #pragma unroll
    for (int i = 0; i < 8; i += 4) {
        const float4 bf = *reinterpret_cast<const float4*>(b_ft  + col + i);
        const float4 bv = *reinterpret_cast<const float4*>(b_fft + col + i);
        const float4 ws = *reinterpret_cast<const float4*>(W_out + col + i);
        const float4 wn = *reinterpret_cast<const float4*>(W_out + FT_OUT + col + i);

        partial += clamp01(acc_s[i+0] + bf.x + bv.x) * ws.x
                 + clamp01(acc_s[i+1] + bf.y + bv.y) * ws.y
                 + clamp01(acc_s[i+2] + bf.z + bv.z) * ws.z
                 + clamp01(acc_s[i+3] + bf.w + bv.w) * ws.w
                 + clamp01(acc_n[i+0] + bf.x + bv.x) * wn.x
                 + clamp01(acc_n[i+1] + bf.y + bv.y) * wn.y
                 + clamp01(acc_n[i+2] + bf.z + bv.z) * wn.z
                 + clamp01(acc_n[i+3] + bf.w + bv.w) * wn.w;
    }

    // block reduction (4 warps)
    #pragma unroll
    for (int off = 16; off > 0; off >>= 1)
        partial += __shfl_xor_sync(0xFFFFFFFFu, partial, off);

    const int warp = t >> 5;
    const int lane = t & 31;
    if (lane == 0) s_red[warp] = partial;
    __syncthreads();

    if (warp == 0) {
        float v = (lane < MAIN_THREADS / 32) ? s_red[lane] : 0.f;
        #pragma unroll
        for (int off = 2; off > 0; off >>= 1)
            v += __shfl_xor_sync(0xFFFFFFFFu, v, off);
        if (lane == 0) {
            const float z = v + b_out[0];
            out[b] = 1.0f / (1.0f + expf(-z));
        }
    }
}

extern "C" void kernel_launch(void* const* d_in, const int* in_sizes, int n_in,
                              void* d_out, int out_size) {
    // metadata order: values, stm_feat, nstm_feat, batch_idx, W_ft, b_ft,
    //                 W_fft, b_fft, W_out, b_out, size
    const float* values    = (const float*)d_in[0];
    const int*   stm_feat  = (const int*)  d_in[1];
    const int*   nstm_feat = (const int*)  d_in[2];
    const float* W_ft      = (const float*)d_in[4];
    const float* b_ft      = (const float*)d_in[5];
    const float* W_fft     = (const float*)d_in[6];
    const float* b_fft     = (const float*)d_in[7];
    const float* W_out     = (const float*)d_in[8];
    const float* b_out     = (const float*)d_in[9];
    float* out = (float*)d_out;

    // Build combined fp16 table (49152*1024/4 threads / 256 = 49152 blocks)
    combine_kernel<<<(N_FEAT * FT_OUT / 4) / 256, 256>>>(W_ft, W_fft);

    nnue_fused_kernel<<<BATCH, MAIN_THREADS>>>(
        values, stm_feat, nstm_feat, b_ft, b_fft, W_out, b_out, out);
}

// round 7
// speedup vs baseline: 2.0378x; 1.0856x over previous
#include <cuda_runtime.h>
#include <cuda_fp16.h>

#define BATCH   8192
#define FPP     32
#define FT_OUT  1024
#define N_FEAT  49152
#define N_VFEAT 768
#define MAIN_THREADS 128

// fp16 combined table: W_comb[r][c] = W_ft[r][c] + W_fft[r % 768][c]
// 49152 x 1024 x 2B = 100,663,296 bytes
__device__ uint4 g_Wcomb[(size_t)N_FEAT * FT_OUT / 8];

__device__ __forceinline__ float clamp01(float x) { return __saturatef(x); }

// ---------------------------------------------------------------------------
// Kernel 1: build combined fp16 table. 8 elements per thread (32B read, 16B
// write). Streaming reads of W_ft so the giant fp32 table doesn't pollute L2;
// default (write-back) stores so the fp16 table is L2-resident for kernel 2.
// ---------------------------------------------------------------------------
__global__ __launch_bounds__(256)
void combine_kernel(const float* __restrict__ W_ft,
                    const float* __restrict__ W_fft)
{
    const int i = blockIdx.x * 256 + threadIdx.x;   // 0 .. 6,291,455
    const int r = i >> 7;                           // 1024/8 = 128 groups/row
    const int c = (i & 127) << 3;

    const float* ft  = W_ft  + (size_t)r * FT_OUT + c;
    const float* fft = W_fft + (size_t)(r % N_VFEAT) * FT_OUT + c;

    const float4 a0 = __ldcs(reinterpret_cast<const float4*>(ft));
    const float4 a1 = __ldcs(reinterpret_cast<const float4*>(ft + 4));
    const float4 v0 = __ldg (reinterpret_cast<const float4*>(fft));
    const float4 v1 = __ldg (reinterpret_cast<const float4*>(fft + 4));

    __half2 h0 = __floats2half2_rn(a0.x + v0.x, a0.y + v0.y);
    __half2 h1 = __floats2half2_rn(a0.z + v0.z, a0.w + v0.w);
    __half2 h2 = __floats2half2_rn(a1.x + v1.x, a1.y + v1.y);
    __half2 h3 = __floats2half2_rn(a1.z + v1.z, a1.w + v1.w);

    uint4 o;
    o.x = *reinterpret_cast<unsigned int*>(&h0);
    o.y = *reinterpret_cast<unsigned int*>(&h1);
    o.z = *reinterpret_cast<unsigned int*>(&h2);
    o.w = *reinterpret_cast<unsigned int*>(&h3);
    g_Wcomb[i] = o;
}

// ---------------------------------------------------------------------------
// Kernel 2: fused gather (HFMA2 accumulation) + bias + clamp + output dot +
// sigmoid. 1 CTA per batch element, 128 threads x 8 columns.
// ---------------------------------------------------------------------------
__global__ __launch_bounds__(MAIN_THREADS, 10)
void nnue_fused_kernel(
    const float* __restrict__ values,
    const int*   __restrict__ stm_feat,
    const int*   __restrict__ nstm_feat,
    const float* __restrict__ b_ft,
    const float* __restrict__ b_fft,
    const float* __restrict__ W_out,
    const float* __restrict__ b_out,
    float*       __restrict__ out)
{
    const int b = blockIdx.x;
    const int t = threadIdx.x;

    __shared__ int   s_stm[FPP];
    __shared__ int   s_nstm[FPP];
    __shared__ float s_val[FPP];
    __shared__ float s_red[MAIN_THREADS / 32];

    if (t < FPP) {
        s_stm[t]  = stm_feat[b * FPP + t];
        s_nstm[t] = nstm_feat[b * FPP + t];
        s_val[t]  = values[b * FPP + t];
    }
    __syncthreads();

    __half2 acc_s[4], acc_n[4];
    #pragma unroll
    for (int i = 0; i < 4; i++) {
        acc_s[i] = __float2half2_rn(0.f);
        acc_n[i] = __float2half2_rn(0.f);
    }

    const uint4* __restrict__ Wc = g_Wcomb;

    #pragma unroll 4
    for (int k = 0; k < FPP; k++) {
        const __half2 vh = __float2half2_rn(s_val[k]);
        const int     fs = s_stm[k];
        const int     fn = s_nstm[k];

        const uint4 us = Wc[(size_t)fs * (FT_OUT / 8) + t];
        const uint4 un = Wc[(size_t)fn * (FT_OUT / 8) + t];

        acc_s[0] = __hfma2(vh, *reinterpret_cast<const __half2*>(&us.x), acc_s[0]);
        acc_s[1] = __hfma2(vh, *reinterpret_cast<const __half2*>(&us.y), acc_s[1]);
        acc_s[2] = __hfma2(vh, *reinterpret_cast<const __half2*>(&us.z), acc_s[2]);
        acc_s[3] = __hfma2(vh, *reinterpret_cast<const __half2*>(&us.w), acc_s[3]);

        acc_n[0] = __hfma2(vh, *reinterpret_cast<const __half2*>(&un.x), acc_n[0]);
        acc_n[1] = __hfma2(vh, *reinterpret_cast<const __half2*>(&un.y), acc_n[1]);
        acc_n[2] = __hfma2(vh, *reinterpret_cast<const __half2*>(&un.z), acc_n[2]);
        acc_n[3] = __hfma2(vh, *reinterpret_cast<const __half2*>(&un.w), acc_n[3]);
    }

    // convert to fp32, add biases (fp32 exact), clamp, fused output dot
    const int col = t * 8;
    float partial = 0.f;
    #pragma unroll
    for (int i = 0; i < 4; i += 2) {
        const float2 as0 = __half22float2(acc_s[i]);
        const float2 as1 = __half22float2(acc_s[i + 1]);
        const float2 an0 = __half22float2(acc_n[i]);
        const float2 an1 = __half22float2(acc_n[i + 1]);

        const int c4 = col + i * 2;
        const float4 bf = *reinterpret_cast<const float4*>(b_ft  + c4);
        const float4 bv = *reinterpret_cast<const float4*>(b_fft + c4);
        const float4 ws = *reinterpret_cast<const float4*>(W_out + c4);
        const float4 wn = *reinterpret_cast<const float4*>(W_out + FT_OUT + c4);

        partial += clamp01(as0.x + bf.x + bv.x) * ws.x
                 + clamp01(as0.y + bf.y + bv.y) * ws.y
                 + clamp01(as1.x + bf.z + bv.z) * ws.z
                 + clamp01(as1.y + bf.w + bv.w) * ws.w
                 + clamp01(an0.x + bf.x + bv.x) * wn.x
                 + clamp01(an0.y + bf.y + bv.y) * wn.y
                 + clamp01(an1.x + bf.z + bv.z) * wn.z
                 + clamp01(an1.y + bf.w + bv.w) * wn.w;
    }

    // block reduction (4 warps)
    #pragma unroll
    for (int off = 16; off > 0; off >>= 1)
        partial += __shfl_xor_sync(0xFFFFFFFFu, partial, off);

    const int warp = t >> 5;
    const int lane = t & 31;
    if (lane == 0) s_red[warp] = partial;
    __syncthreads();

    if (warp == 0) {
        float v = (lane < MAIN_THREADS / 32) ? s_red[lane] : 0.f;
        #pragma unroll
        for (int off = 2; off > 0; off >>= 1)
            v += __shfl_xor_sync(0xFFFFFFFFu, v, off);
        if (lane == 0) {
            const float z = v + b_out[0];
            out[b] = 1.0f / (1.0f + expf(-z));
        }
    }
}

extern "C" void kernel_launch(void* const* d_in, const int* in_sizes, int n_in,
                              void* d_out, int out_size) {
    // metadata order: values, stm_feat, nstm_feat, batch_idx, W_ft, b_ft,
    //                 W_fft, b_fft, W_out, b_out, size
    const float* values    = (const float*)d_in[0];
    const int*   stm_feat  = (const int*)  d_in[1];
    const int*   nstm_feat = (const int*)  d_in[2];
    const float* W_ft      = (const float*)d_in[4];
    const float* b_ft      = (const float*)d_in[5];
    const float* W_fft     = (const float*)d_in[6];
    const float* b_fft     = (const float*)d_in[7];
    const float* W_out     = (const float*)d_in[8];
    const float* b_out     = (const float*)d_in[9];
    float* out = (float*)d_out;

    // 49152*1024/8 elems-of-8 / 256 threads = 24576 blocks
    combine_kernel<<<(N_FEAT * (FT_OUT / 8)) / 256, 256>>>(W_ft, W_fft);

    nnue_fused_kernel<<<BATCH, MAIN_THREADS>>>(
        values, stm_feat, nstm_feat, b_ft, b_fft, W_out, b_out, out);
}